// round 2
// baseline (speedup 1.0000x reference)
#include <cuda_runtime.h>
#include <math.h>
#include <stdint.h>

// ---------------- problem constants ----------------
#define BB   512
#define NN   196          // 14*14
#define NQ   49           // 7*7
#define CC   256
#define HH   8
#define KD   16
#define VD   32
#define KV_DIM 384        // H*(KD+VD)
#define Q_DIM  128        // H*KD
#define V_ATTN 256        // H*VD
#define OUT_DIM 384
#define EPS  1e-5f
#define ATT_SCALE 0.25f   // 16^-0.5

// ---------------- scratch (module-static, allowed) ----------------
__device__ float g_kv_buf[(size_t)BB * NN * KV_DIM];   // 154 MB
__device__ float g_q_buf [(size_t)BB * NQ * Q_DIM];    // 12.8 MB
__device__ float g_o_buf [(size_t)BB * NQ * V_ATTN];   // 25.7 MB

__device__ __forceinline__ float hswish(float x) {
    float c = fminf(fmaxf(x + 3.0f, 0.0f), 6.0f);
    return x * c * (1.0f / 6.0f);
}

// ---------------------------------------------------------------------------
// Fused GEMM + batchnorm-style epilogue, software-pipelined mainloop.
//   out[m,n] = (sum_k A'[m,k] * W[n,k] - mv[n]) * gv[n]*rsqrt(vv[n]+eps) + bv[n]
// MODE 0: A' = A (x, row-major [M,256])
// MODE 1: A' = strided 2x subsample of x (query gather), rows indexed b*49+qq
// MODE 2: A' = hardswish(A)  (A = g_o_buf)
// Tile: 128x128, K-chunk 8, 256 threads, 8x8 per-thread microtile.
// ---------------------------------------------------------------------------
template <int MODE>
__global__ __launch_bounds__(256, 2)
void gemm_norm(const float* __restrict__ A, const float* __restrict__ W,
               const float* __restrict__ gv, const float* __restrict__ bv,
               const float* __restrict__ mv, const float* __restrict__ vv,
               float* __restrict__ out, int Ncols)
{
    __shared__ float As[8][128];
    __shared__ float Bs[8][128];

    const int t  = threadIdx.x;
    const int tx = t & 15;        // 0..15  -> n sub-tile
    const int ty = t >> 4;        // 0..15  -> m sub-tile
    const int m0 = blockIdx.y * 128;
    const int n0 = blockIdx.x * 128;

    // loader indices: 128 rows x 8 k, each thread one float4
    const int lr = t >> 1;        // row within tile (0..127)
    const int lk = (t & 1) * 4;   // k offset (0 or 4)

    const float* Arow;
    {
        int gm = m0 + lr;
        if (MODE == 1) {
            int b  = gm / NQ;
            int qq = gm - b * NQ;
            int n  = 28 * (qq / 7) + 2 * (qq % 7);   // (2*qi)*14 + 2*qj
            Arow = A + ((size_t)(b * NN + n)) * CC;
        } else {
            Arow = A + (size_t)gm * CC;
        }
    }
    const float* Brow = W + (size_t)(n0 + lr) * CC;

    float acc[8][8];
#pragma unroll
    for (int i = 0; i < 8; i++)
#pragma unroll
        for (int j = 0; j < 8; j++) acc[i][j] = 0.0f;

    // ---- pipelined mainloop: prefetch chunk k0+8 while computing chunk k0 ----
    float4 a4 = *(const float4*)(Arow + lk);
    float4 b4 = *(const float4*)(Brow + lk);
    if (MODE == 2) {
        a4.x = hswish(a4.x); a4.y = hswish(a4.y);
        a4.z = hswish(a4.z); a4.w = hswish(a4.w);
    }

    for (int k0 = 0; k0 < CC; k0 += 8) {
        __syncthreads();   // previous compute done reading smem
        As[lk + 0][lr] = a4.x; As[lk + 1][lr] = a4.y;
        As[lk + 2][lr] = a4.z; As[lk + 3][lr] = a4.w;
        Bs[lk + 0][lr] = b4.x; Bs[lk + 1][lr] = b4.y;
        Bs[lk + 2][lr] = b4.z; Bs[lk + 3][lr] = b4.w;
        __syncthreads();

        if (k0 + 8 < CC) {  // issue next loads before compute (latency hiding)
            a4 = *(const float4*)(Arow + k0 + 8 + lk);
            b4 = *(const float4*)(Brow + k0 + 8 + lk);
            if (MODE == 2) {
                a4.x = hswish(a4.x); a4.y = hswish(a4.y);
                a4.z = hswish(a4.z); a4.w = hswish(a4.w);
            }
        }

#pragma unroll
        for (int kk = 0; kk < 8; kk++) {
            float a[8], b[8];
            *(float4*)&a[0] = *(const float4*)&As[kk][ty * 8];
            *(float4*)&a[4] = *(const float4*)&As[kk][ty * 8 + 4];
            *(float4*)&b[0] = *(const float4*)&Bs[kk][tx * 8];
            *(float4*)&b[4] = *(const float4*)&Bs[kk][tx * 8 + 4];
#pragma unroll
            for (int i = 0; i < 8; i++)
#pragma unroll
                for (int j = 0; j < 8; j++)
                    acc[i][j] += a[i] * b[j];
        }
    }

    // epilogue: per-column norm params, vectorized stores
    float sc[8], mm[8], bo[8];
#pragma unroll
    for (int j = 0; j < 8; j++) {
        int n = n0 + tx * 8 + j;
        sc[j] = gv[n] * rsqrtf(vv[n] + EPS);
        mm[j] = mv[n];
        bo[j] = bv[n];
    }
    const int gmBase = m0 + ty * 8;
#pragma unroll
    for (int i = 0; i < 8; i++) {
        float tmp[8];
#pragma unroll
        for (int j = 0; j < 8; j++)
            tmp[j] = (acc[i][j] - mm[j]) * sc[j] + bo[j];
        float* dst = out + (size_t)(gmBase + i) * Ncols + n0 + tx * 8;
        *(float4*)(dst)     = *(float4*)&tmp[0];
        *(float4*)(dst + 4) = *(float4*)&tmp[4];
    }
}

// ---------------------------------------------------------------------------
// Attention: one block per (batch, head). 256 threads = 8 warps.
// Stages k (196x16, padded 17), v (196x32), q (49x16), bias row (196) in smem.
// One warp per query row: logits + biased softmax + p@v with lane = vd.
// ---------------------------------------------------------------------------
__global__ __launch_bounds__(256)
void attn_kernel(const float* __restrict__ biases, const int* __restrict__ bias_idxs)
{
    __shared__ float ks[NN * 17];       // padded stride 17 -> conflict-free dot
    __shared__ float vs[NN * VD];
    __shared__ float qs[NQ * KD];
    __shared__ float bs[NN];
    __shared__ float ps[8 * NN];

    const int bh = blockIdx.x;
    const int b = bh >> 3, h = bh & 7;
    const int t = threadIdx.x;

    const float* kvbase = g_kv_buf + (size_t)b * NN * KV_DIM + h * (KD + VD);
    for (int idx = t; idx < NN * KD; idx += 256) {
        int n = idx >> 4, d = idx & 15;
        ks[n * 17 + d] = kvbase[n * KV_DIM + d];
    }
    for (int idx = t; idx < NN * VD; idx += 256) {
        int n = idx >> 5, d = idx & 31;
        vs[idx] = kvbase[n * KV_DIM + KD + d];
    }
    const float* qbase = g_q_buf + (size_t)b * NQ * Q_DIM + h * KD;
    for (int idx = t; idx < NQ * KD; idx += 256) {
        int n = idx >> 4, d = idx & 15;
        qs[idx] = qbase[n * Q_DIM + d];
    }
    for (int idx = t; idx < NN; idx += 256)
        bs[idx] = biases[h * NN + idx];
    __syncthreads();

    const int w = t >> 5, lane = t & 31;

    for (int q = w; q < NQ; q += 8) {
        float lg[7];
        float mx = -1e30f;
#pragma unroll
        for (int s = 0; s < 7; s++) {
            int k = lane + 32 * s;
            if (k < NN) {
                float d0 = 0.0f;
#pragma unroll
                for (int d = 0; d < KD; d++)
                    d0 += qs[q * KD + d] * ks[k * 17 + d];
                int bi = bias_idxs[q * NN + k];
                lg[s] = d0 * ATT_SCALE + bs[bi];
                mx = fmaxf(mx, lg[s]);
            } else {
                lg[s] = -1e30f;
            }
        }
#pragma unroll
        for (int o = 16; o > 0; o >>= 1)
            mx = fmaxf(mx, __shfl_xor_sync(0xffffffffu, mx, o));
        float sum = 0.0f;
#pragma unroll
        for (int s = 0; s < 7; s++) {
            int k = lane + 32 * s;
            if (k < NN) { lg[s] = expf(lg[s] - mx); sum += lg[s]; }
        }
#pragma unroll
        for (int o = 16; o > 0; o >>= 1)
            sum += __shfl_xor_sync(0xffffffffu, sum, o);
        float inv = 1.0f / sum;
#pragma unroll
        for (int s = 0; s < 7; s++) {
            int k = lane + 32 * s;
            if (k < NN) ps[w * NN + k] = lg[s] * inv;
        }
        __syncwarp();
        // o[q, vd=lane] = sum_k p[k] * v[k, lane]
        float ov = 0.0f;
#pragma unroll 4
        for (int k = 0; k < NN; k++)
            ov += ps[w * NN + k] * vs[k * VD + lane];
        g_o_buf[((size_t)(b * NQ + q)) * V_ATTN + h * VD + lane] = ov;
        __syncwarp();
    }
}

// ---------------------------------------------------------------------------
extern "C" void kernel_launch(void* const* d_in, const int* in_sizes, int n_in,
                              void* d_out, int out_size)
{
    const float* x      = (const float*)d_in[0];
    const float* W_kv   = (const float*)d_in[1];
    const float* gkv    = (const float*)d_in[2];
    const float* bkv    = (const float*)d_in[3];
    const float* mkv    = (const float*)d_in[4];
    const float* vkv    = (const float*)d_in[5];
    const float* W_q    = (const float*)d_in[6];
    const float* gq     = (const float*)d_in[7];
    const float* bq     = (const float*)d_in[8];
    const float* mq     = (const float*)d_in[9];
    const float* vq     = (const float*)d_in[10];
    const float* W_proj = (const float*)d_in[11];
    const float* gp     = (const float*)d_in[12];
    const float* bp     = (const float*)d_in[13];
    const float* mp     = (const float*)d_in[14];
    const float* vp     = (const float*)d_in[15];
    const float* biases = (const float*)d_in[16];
    const int*   bidx   = (const int*)  d_in[17];

    float *kvp, *qp, *op;
    cudaGetSymbolAddress((void**)&kvp, g_kv_buf);
    cudaGetSymbolAddress((void**)&qp,  g_q_buf);
    cudaGetSymbolAddress((void**)&op,  g_o_buf);

    // K1: kv = linear_norm(x, W_kv)  -- M=100352, N=384, K=256
    gemm_norm<0><<<dim3(KV_DIM / 128, (BB * NN) / 128), 256>>>(
        x, W_kv, gkv, bkv, mkv, vkv, kvp, KV_DIM);

    // K2: q = linear_norm(subsample(x), W_q) -- M=25088, N=128, K=256
    gemm_norm<1><<<dim3(Q_DIM / 128, (BB * NQ) / 128), 256>>>(
        x, W_q, gq, bq, mq, vq, qp, Q_DIM);

    // K3: attention per (b, h)
    attn_kernel<<<BB * HH, 256>>>(biases, bidx);

    // K4: out = linear_norm(hardswish(o), W_proj) -- M=25088, N=384, K=256
    gemm_norm<2><<<dim3(OUT_DIM / 128, (BB * NQ) / 128), 256>>>(
        op, W_proj, gp, bp, mp, vp, (float*)d_out, OUT_DIM);
}

// round 4
// speedup vs baseline: 1.4901x; 1.4901x over previous
#include <cuda_runtime.h>
#include <math.h>
#include <stdint.h>

// ---------------- problem constants ----------------
#define BB   512
#define NN   196          // 14*14
#define NQ   49           // 7*7
#define CC   256
#define HH   8
#define KD   16
#define VD   32
#define KV_DIM 384        // H*(KD+VD)
#define Q_DIM  128        // H*KD
#define V_ATTN 256        // H*VD
#define OUT_DIM 384
#define EPS  1e-5f
#define ATT_SCALE 0.25f   // 16^-0.5

// ---------------- scratch (module-static, allowed) ----------------
__device__ float g_kv_buf[(size_t)BB * NN * KV_DIM];   // 154 MB
__device__ float g_q_buf [(size_t)BB * NQ * Q_DIM];    // 12.8 MB
__device__ float g_o_buf [(size_t)BB * NQ * V_ATTN];   // 25.7 MB

__device__ __forceinline__ float hswish(float x) {
    float c = fminf(fmaxf(x + 3.0f, 0.0f), 6.0f);
    return x * c * (1.0f / 6.0f);
}

__device__ __forceinline__ uint32_t f2tf(float x) {
    uint32_t r;
    asm("cvt.rna.tf32.f32 %0, %1;" : "=r"(r) : "f"(x));
    return r;
}

__device__ __forceinline__ void mma_tf32(float* c, const uint32_t* a,
                                         uint32_t b0, uint32_t b1) {
    asm volatile(
        "mma.sync.aligned.m16n8k8.row.col.f32.tf32.tf32.f32 "
        "{%0,%1,%2,%3}, {%4,%5,%6,%7}, {%8,%9}, {%0,%1,%2,%3};\n"
        : "+f"(c[0]), "+f"(c[1]), "+f"(c[2]), "+f"(c[3])
        : "r"(a[0]), "r"(a[1]), "r"(a[2]), "r"(a[3]), "r"(b0), "r"(b1));
}

// ---------------------------------------------------------------------------
// TF32 tensor-core GEMM + norm epilogue.
//   out[m,n] = (sum_k A'[m,k]*W[n,k] - mv[n]) * gv[n]*rsqrt(vv[n]+eps) + bv[n]
// MODE 0: A' = A;  MODE 1: A' = 2x-strided subsample gather of x.
// Tile 128x128, BK=16, 8 warps (4x2), warp tile 32x64 of m16n8k8 frags.
// Double-buffered smem (stride 20 -> conflict-free frag loads).
// ---------------------------------------------------------------------------
template <int MODE>
__global__ __launch_bounds__(256)
void gemm_tf32(const float* __restrict__ A, const float* __restrict__ W,
               const float* __restrict__ gv, const float* __restrict__ bv,
               const float* __restrict__ mv, const float* __restrict__ vv,
               float* __restrict__ out, int Ncols)
{
    __shared__ uint32_t As[2][128][20];
    __shared__ uint32_t Bs[2][128][20];

    const int t    = threadIdx.x;
    const int lane = t & 31;
    const int warp = t >> 5;
    const int wm   = warp >> 1;          // 0..3 -> m offset 32*wm
    const int wn   = warp & 1;           // 0..1 -> n offset 64*wn
    const int m0   = blockIdx.y * 128;
    const int n0   = blockIdx.x * 128;

    // loader: each thread loads 2 float4 for A and 2 for B per chunk
    const int lrow = t >> 2;             // 0..63
    const int lk4  = (t & 3) * 4;        // 0,4,8,12

    const float* Aptr[2];
#pragma unroll
    for (int r = 0; r < 2; r++) {
        int gm = m0 + lrow + r * 64;
        if (MODE == 1) {
            int b  = gm / NQ;
            int qq = gm - b * NQ;
            int n  = 28 * (qq / 7) + 2 * (qq % 7);
            Aptr[r] = A + ((size_t)(b * NN + n)) * CC;
        } else {
            Aptr[r] = A + (size_t)gm * CC;
        }
    }
    const float* Bptr[2];
#pragma unroll
    for (int r = 0; r < 2; r++)
        Bptr[r] = W + (size_t)(n0 + lrow + r * 64) * CC;

    float acc[2][8][4];
#pragma unroll
    for (int i = 0; i < 2; i++)
#pragma unroll
        for (int j = 0; j < 8; j++)
#pragma unroll
            for (int k = 0; k < 4; k++) acc[i][j][k] = 0.0f;

    float4 av[2], bv4[2];
#pragma unroll
    for (int r = 0; r < 2; r++) {
        av[r]  = *(const float4*)(Aptr[r] + lk4);
        bv4[r] = *(const float4*)(Bptr[r] + lk4);
    }

    int buf = 0;
    const int lq = lane >> 2;            // lane/4
    const int lr4 = lane & 3;            // lane%4

    for (int c = 0; c < CC / 16; c++) {
        // store staged regs (as tf32 bits)
#pragma unroll
        for (int r = 0; r < 2; r++) {
            int row = lrow + r * 64;
            As[buf][row][lk4 + 0] = f2tf(av[r].x);
            As[buf][row][lk4 + 1] = f2tf(av[r].y);
            As[buf][row][lk4 + 2] = f2tf(av[r].z);
            As[buf][row][lk4 + 3] = f2tf(av[r].w);
            Bs[buf][row][lk4 + 0] = f2tf(bv4[r].x);
            Bs[buf][row][lk4 + 1] = f2tf(bv4[r].y);
            Bs[buf][row][lk4 + 2] = f2tf(bv4[r].z);
            Bs[buf][row][lk4 + 3] = f2tf(bv4[r].w);
        }
        __syncthreads();

        if (c + 1 < CC / 16) {           // prefetch next chunk
            int k0 = (c + 1) * 16;
#pragma unroll
            for (int r = 0; r < 2; r++) {
                av[r]  = *(const float4*)(Aptr[r] + k0 + lk4);
                bv4[r] = *(const float4*)(Bptr[r] + k0 + lk4);
            }
        }

        // compute on this buffer: 2 k-steps of 8
#pragma unroll
        for (int ks = 0; ks < 16; ks += 8) {
            uint32_t a[2][4];
#pragma unroll
            for (int mt = 0; mt < 2; mt++) {
                int mb = wm * 32 + mt * 16;
                a[mt][0] = As[buf][mb + lq    ][ks + lr4];
                a[mt][1] = As[buf][mb + lq + 8][ks + lr4];
                a[mt][2] = As[buf][mb + lq    ][ks + lr4 + 4];
                a[mt][3] = As[buf][mb + lq + 8][ks + lr4 + 4];
            }
#pragma unroll
            for (int nt = 0; nt < 8; nt++) {
                int nb = wn * 64 + nt * 8;
                uint32_t b0 = Bs[buf][nb + lq][ks + lr4];
                uint32_t b1 = Bs[buf][nb + lq][ks + lr4 + 4];
                mma_tf32(acc[0][nt], a[0], b0, b1);
                mma_tf32(acc[1][nt], a[1], b0, b1);
            }
        }
        buf ^= 1;
    }

    // epilogue
#pragma unroll
    for (int mt = 0; mt < 2; mt++) {
        int mrow = m0 + wm * 32 + mt * 16 + lq;
#pragma unroll
        for (int nt = 0; nt < 8; nt++) {
            int n = n0 + wn * 64 + nt * 8 + lr4 * 2;
            float s0 = gv[n]     * rsqrtf(vv[n]     + EPS);
            float s1 = gv[n + 1] * rsqrtf(vv[n + 1] + EPS);
            float m_0 = mv[n], m_1 = mv[n + 1];
            float o_0 = bv[n], o_1 = bv[n + 1];
            const float* cc = acc[mt][nt];
            float2 r0 = { (cc[0] - m_0) * s0 + o_0, (cc[1] - m_1) * s1 + o_1 };
            float2 r1 = { (cc[2] - m_0) * s0 + o_0, (cc[3] - m_1) * s1 + o_1 };
            *(float2*)(out + (size_t)mrow * Ncols + n)       = r0;
            *(float2*)(out + (size_t)(mrow + 8) * Ncols + n) = r1;
        }
    }
}

// ---------------------------------------------------------------------------
// FP32 SIMT GEMM + norm epilogue (kept exact for the final projection, MODE 2
// = hardswish on A). Software-pipelined, 128x128 tile, 8x8 microtile.
// ---------------------------------------------------------------------------
template <int MODE>
__global__ __launch_bounds__(256, 2)
void gemm_norm(const float* __restrict__ A, const float* __restrict__ W,
               const float* __restrict__ gv, const float* __restrict__ bv,
               const float* __restrict__ mv, const float* __restrict__ vv,
               float* __restrict__ out, int Ncols)
{
    __shared__ float As[8][128];
    __shared__ float Bs[8][128];

    const int t  = threadIdx.x;
    const int tx = t & 15;
    const int ty = t >> 4;
    const int m0 = blockIdx.y * 128;
    const int n0 = blockIdx.x * 128;

    const int lr = t >> 1;
    const int lk = (t & 1) * 4;

    const float* Arow = A + (size_t)(m0 + lr) * CC;
    const float* Brow = W + (size_t)(n0 + lr) * CC;

    float acc[8][8];
#pragma unroll
    for (int i = 0; i < 8; i++)
#pragma unroll
        for (int j = 0; j < 8; j++) acc[i][j] = 0.0f;

    float4 a4 = *(const float4*)(Arow + lk);
    float4 b4 = *(const float4*)(Brow + lk);
    if (MODE == 2) {
        a4.x = hswish(a4.x); a4.y = hswish(a4.y);
        a4.z = hswish(a4.z); a4.w = hswish(a4.w);
    }

    for (int k0 = 0; k0 < CC; k0 += 8) {
        __syncthreads();
        As[lk + 0][lr] = a4.x; As[lk + 1][lr] = a4.y;
        As[lk + 2][lr] = a4.z; As[lk + 3][lr] = a4.w;
        Bs[lk + 0][lr] = b4.x; Bs[lk + 1][lr] = b4.y;
        Bs[lk + 2][lr] = b4.z; Bs[lk + 3][lr] = b4.w;
        __syncthreads();

        if (k0 + 8 < CC) {
            a4 = *(const float4*)(Arow + k0 + 8 + lk);
            b4 = *(const float4*)(Brow + k0 + 8 + lk);
            if (MODE == 2) {
                a4.x = hswish(a4.x); a4.y = hswish(a4.y);
                a4.z = hswish(a4.z); a4.w = hswish(a4.w);
            }
        }

#pragma unroll
        for (int kk = 0; kk < 8; kk++) {
            float a[8], b[8];
            *(float4*)&a[0] = *(const float4*)&As[kk][ty * 8];
            *(float4*)&a[4] = *(const float4*)&As[kk][ty * 8 + 4];
            *(float4*)&b[0] = *(const float4*)&Bs[kk][tx * 8];
            *(float4*)&b[4] = *(const float4*)&Bs[kk][tx * 8 + 4];
#pragma unroll
            for (int i = 0; i < 8; i++)
#pragma unroll
                for (int j = 0; j < 8; j++)
                    acc[i][j] += a[i] * b[j];
        }
    }

    float sc[8], mm[8], bo[8];
#pragma unroll
    for (int j = 0; j < 8; j++) {
        int n = n0 + tx * 8 + j;
        sc[j] = gv[n] * rsqrtf(vv[n] + EPS);
        mm[j] = mv[n];
        bo[j] = bv[n];
    }
    const int gmBase = m0 + ty * 8;
#pragma unroll
    for (int i = 0; i < 8; i++) {
        float tmp[8];
#pragma unroll
        for (int j = 0; j < 8; j++)
            tmp[j] = (acc[i][j] - mm[j]) * sc[j] + bo[j];
        float* dst = out + (size_t)(gmBase + i) * Ncols + n0 + tx * 8;
        *(float4*)(dst)     = *(float4*)&tmp[0];
        *(float4*)(dst + 4) = *(float4*)&tmp[4];
    }
}

// ---------------------------------------------------------------------------
// Attention: one block per (batch, head). 256 threads = 8 warps.
// ---------------------------------------------------------------------------
__global__ __launch_bounds__(256)
void attn_kernel(const float* __restrict__ biases, const int* __restrict__ bias_idxs)
{
    __shared__ float ks[NN * 17];
    __shared__ float vs[NN * VD];
    __shared__ float qs[NQ * KD];
    __shared__ float bs[NN];
    __shared__ float ps[8 * NN];

    const int bh = blockIdx.x;
    const int b = bh >> 3, h = bh & 7;
    const int t = threadIdx.x;

    const float* kvbase = g_kv_buf + (size_t)b * NN * KV_DIM + h * (KD + VD);
    for (int idx = t; idx < NN * KD; idx += 256) {
        int n = idx >> 4, d = idx & 15;
        ks[n * 17 + d] = kvbase[n * KV_DIM + d];
    }
    for (int idx = t; idx < NN * VD; idx += 256) {
        int n = idx >> 5, d = idx & 31;
        vs[idx] = kvbase[n * KV_DIM + KD + d];
    }
    const float* qbase = g_q_buf + (size_t)b * NQ * Q_DIM + h * KD;
    for (int idx = t; idx < NQ * KD; idx += 256) {
        int n = idx >> 4, d = idx & 15;
        qs[idx] = qbase[n * Q_DIM + d];
    }
    for (int idx = t; idx < NN; idx += 256)
        bs[idx] = biases[h * NN + idx];
    __syncthreads();

    const int w = t >> 5, lane = t & 31;

    for (int q = w; q < NQ; q += 8) {
        float lg[7];
        float mx = -1e30f;
#pragma unroll
        for (int s = 0; s < 7; s++) {
            int k = lane + 32 * s;
            if (k < NN) {
                float d0 = 0.0f;
#pragma unroll
                for (int d = 0; d < KD; d++)
                    d0 += qs[q * KD + d] * ks[k * 17 + d];
                int bi = bias_idxs[q * NN + k];
                lg[s] = d0 * ATT_SCALE + bs[bi];
                mx = fmaxf(mx, lg[s]);
            } else {
                lg[s] = -1e30f;
            }
        }
#pragma unroll
        for (int o = 16; o > 0; o >>= 1)
            mx = fmaxf(mx, __shfl_xor_sync(0xffffffffu, mx, o));
        float sum = 0.0f;
#pragma unroll
        for (int s = 0; s < 7; s++) {
            int k = lane + 32 * s;
            if (k < NN) { lg[s] = expf(lg[s] - mx); sum += lg[s]; }
        }
#pragma unroll
        for (int o = 16; o > 0; o >>= 1)
            sum += __shfl_xor_sync(0xffffffffu, sum, o);
        float inv = 1.0f / sum;
#pragma unroll
        for (int s = 0; s < 7; s++) {
            int k = lane + 32 * s;
            if (k < NN) ps[w * NN + k] = lg[s] * inv;
        }
        __syncwarp();
        float ov = 0.0f;
#pragma unroll 4
        for (int k = 0; k < NN; k++)
            ov += ps[w * NN + k] * vs[k * VD + lane];
        g_o_buf[((size_t)(b * NQ + q)) * V_ATTN + h * VD + lane] = ov;
        __syncwarp();
    }
}

// ---------------------------------------------------------------------------
extern "C" void kernel_launch(void* const* d_in, const int* in_sizes, int n_in,
                              void* d_out, int out_size)
{
    const float* x      = (const float*)d_in[0];
    const float* W_kv   = (const float*)d_in[1];
    const float* gkv    = (const float*)d_in[2];
    const float* bkv    = (const float*)d_in[3];
    const float* mkv    = (const float*)d_in[4];
    const float* vkv    = (const float*)d_in[5];
    const float* W_q    = (const float*)d_in[6];
    const float* gq     = (const float*)d_in[7];
    const float* bq     = (const float*)d_in[8];
    const float* mq     = (const float*)d_in[9];
    const float* vq     = (const float*)d_in[10];
    const float* W_proj = (const float*)d_in[11];
    const float* gp     = (const float*)d_in[12];
    const float* bp     = (const float*)d_in[13];
    const float* mp     = (const float*)d_in[14];
    const float* vp     = (const float*)d_in[15];
    const float* biases = (const float*)d_in[16];
    const int*   bidx   = (const int*)  d_in[17];

    float *kvp, *qp, *op;
    cudaGetSymbolAddress((void**)&kvp, g_kv_buf);
    cudaGetSymbolAddress((void**)&qp,  g_q_buf);
    cudaGetSymbolAddress((void**)&op,  g_o_buf);

    // K1: kv = linear_norm(x, W_kv)  -- M=100352, N=384, K=256  (tf32 MMA)
    gemm_tf32<0><<<dim3(KV_DIM / 128, (BB * NN) / 128), 256>>>(
        x, W_kv, gkv, bkv, mkv, vkv, kvp, KV_DIM);

    // K2: q = linear_norm(subsample(x), W_q) -- M=25088, N=128 (tf32 MMA)
    gemm_tf32<1><<<dim3(Q_DIM / 128, (BB * NQ) / 128), 256>>>(
        x, W_q, gq, bq, mq, vq, qp, Q_DIM);

    // K3: attention per (b, h)
    attn_kernel<<<BB * HH, 256>>>(biases, bidx);

    // K4: out = linear_norm(hardswish(o), W_proj) -- exact fp32
    gemm_norm<2><<<dim3(OUT_DIM / 128, (BB * NQ) / 128), 256>>>(
        op, W_proj, gp, bp, mp, vp, (float*)d_out, OUT_DIM);
}

// round 5
// speedup vs baseline: 1.5395x; 1.0332x over previous
#include <cuda_runtime.h>
#include <math.h>
#include <stdint.h>

// ---------------- problem constants ----------------
#define BB   512
#define NN   196          // 14*14
#define NQ   49           // 7*7
#define CC   256
#define HH   8
#define KD   16
#define VD   32
#define KV_DIM 384        // H*(KD+VD)
#define Q_DIM  128        // H*KD
#define V_ATTN 256        // H*VD
#define OUT_DIM 384
#define EPS  1e-5f
#define ATT_SCALE 0.25f   // 16^-0.5

// ---------------- scratch (module-static, allowed) ----------------
__device__ float g_kv_buf[(size_t)BB * NN * KV_DIM];   // 154 MB
__device__ float g_q_buf [(size_t)BB * NQ * Q_DIM];    // 12.8 MB
__device__ float g_o_buf [(size_t)BB * NQ * V_ATTN];   // 25.7 MB
__device__ float g_bias_buf[HH * NQ * NN];             // 307 KB

__device__ __forceinline__ float hswish(float x) {
    float c = fminf(fmaxf(x + 3.0f, 0.0f), 6.0f);
    return x * c * (1.0f / 6.0f);
}

__device__ __forceinline__ uint32_t f2tf(float x) {
    uint32_t r;
    asm("cvt.rna.tf32.f32 %0, %1;" : "=r"(r) : "f"(x));
    return r;
}

__device__ __forceinline__ void mma_tf32(float* c, const uint32_t* a,
                                         uint32_t b0, uint32_t b1) {
    asm volatile(
        "mma.sync.aligned.m16n8k8.row.col.f32.tf32.tf32.f32 "
        "{%0,%1,%2,%3}, {%4,%5,%6,%7}, {%8,%9}, {%0,%1,%2,%3};\n"
        : "+f"(c[0]), "+f"(c[1]), "+f"(c[2]), "+f"(c[3])
        : "r"(a[0]), "r"(a[1]), "r"(a[2]), "r"(a[3]), "r"(b0), "r"(b1));
}

// ---------------------------------------------------------------------------
// TF32 tensor-core GEMM + norm epilogue.
//   out[m,n] = (sum_k A'[m,k]*W[n,k] - mv[n]) * gv[n]*rsqrt(vv[n]+eps) + bv[n]
// MODE 0: A' = A;  MODE 1: A' = 2x-strided subsample gather of x.
// MODE 2: A' = hardswish(A).
// Tile 128x128, BK=16, 8 warps (4x2), warp tile 32x64 of m16n8k8 frags.
// Double-buffered smem (stride 20 -> conflict-free frag loads).
// ---------------------------------------------------------------------------
template <int MODE>
__global__ __launch_bounds__(256)
void gemm_tf32(const float* __restrict__ A, const float* __restrict__ W,
               const float* __restrict__ gv, const float* __restrict__ bv,
               const float* __restrict__ mv, const float* __restrict__ vv,
               float* __restrict__ out, int Ncols)
{
    __shared__ uint32_t As[2][128][20];
    __shared__ uint32_t Bs[2][128][20];

    const int t    = threadIdx.x;
    const int lane = t & 31;
    const int warp = t >> 5;
    const int wm   = warp >> 1;          // 0..3 -> m offset 32*wm
    const int wn   = warp & 1;           // 0..1 -> n offset 64*wn
    const int m0   = blockIdx.y * 128;
    const int n0   = blockIdx.x * 128;

    // loader: each thread loads 2 float4 for A and 2 for B per chunk
    const int lrow = t >> 2;             // 0..63
    const int lk4  = (t & 3) * 4;        // 0,4,8,12

    const float* Aptr[2];
#pragma unroll
    for (int r = 0; r < 2; r++) {
        int gm = m0 + lrow + r * 64;
        if (MODE == 1) {
            int b  = gm / NQ;
            int qq = gm - b * NQ;
            int n  = 28 * (qq / 7) + 2 * (qq % 7);
            Aptr[r] = A + ((size_t)(b * NN + n)) * CC;
        } else {
            Aptr[r] = A + (size_t)gm * CC;
        }
    }
    const float* Bptr[2];
#pragma unroll
    for (int r = 0; r < 2; r++)
        Bptr[r] = W + (size_t)(n0 + lrow + r * 64) * CC;

    float acc[2][8][4];
#pragma unroll
    for (int i = 0; i < 2; i++)
#pragma unroll
        for (int j = 0; j < 8; j++)
#pragma unroll
            for (int k = 0; k < 4; k++) acc[i][j][k] = 0.0f;

    float4 av[2], bv4[2];
#pragma unroll
    for (int r = 0; r < 2; r++) {
        av[r]  = *(const float4*)(Aptr[r] + lk4);
        bv4[r] = *(const float4*)(Bptr[r] + lk4);
    }

    int buf = 0;
    const int lq = lane >> 2;            // lane/4
    const int lr4 = lane & 3;            // lane%4

    for (int c = 0; c < CC / 16; c++) {
        // store staged regs (as tf32 bits), hardswish fused for MODE 2
#pragma unroll
        for (int r = 0; r < 2; r++) {
            int row = lrow + r * 64;
            float4 a = av[r];
            if (MODE == 2) {
                a.x = hswish(a.x); a.y = hswish(a.y);
                a.z = hswish(a.z); a.w = hswish(a.w);
            }
            As[buf][row][lk4 + 0] = f2tf(a.x);
            As[buf][row][lk4 + 1] = f2tf(a.y);
            As[buf][row][lk4 + 2] = f2tf(a.z);
            As[buf][row][lk4 + 3] = f2tf(a.w);
            Bs[buf][row][lk4 + 0] = f2tf(bv4[r].x);
            Bs[buf][row][lk4 + 1] = f2tf(bv4[r].y);
            Bs[buf][row][lk4 + 2] = f2tf(bv4[r].z);
            Bs[buf][row][lk4 + 3] = f2tf(bv4[r].w);
        }
        __syncthreads();

        if (c + 1 < CC / 16) {           // prefetch next chunk
            int k0 = (c + 1) * 16;
#pragma unroll
            for (int r = 0; r < 2; r++) {
                av[r]  = *(const float4*)(Aptr[r] + k0 + lk4);
                bv4[r] = *(const float4*)(Bptr[r] + k0 + lk4);
            }
        }

        // compute on this buffer: 2 k-steps of 8
#pragma unroll
        for (int ks = 0; ks < 16; ks += 8) {
            uint32_t a[2][4];
#pragma unroll
            for (int mt = 0; mt < 2; mt++) {
                int mb = wm * 32 + mt * 16;
                a[mt][0] = As[buf][mb + lq    ][ks + lr4];
                a[mt][1] = As[buf][mb + lq + 8][ks + lr4];
                a[mt][2] = As[buf][mb + lq    ][ks + lr4 + 4];
                a[mt][3] = As[buf][mb + lq + 8][ks + lr4 + 4];
            }
#pragma unroll
            for (int nt = 0; nt < 8; nt++) {
                int nb = wn * 64 + nt * 8;
                uint32_t b0 = Bs[buf][nb + lq][ks + lr4];
                uint32_t b1 = Bs[buf][nb + lq][ks + lr4 + 4];
                mma_tf32(acc[0][nt], a[0], b0, b1);
                mma_tf32(acc[1][nt], a[1], b0, b1);
            }
        }
        buf ^= 1;
    }

    // epilogue
#pragma unroll
    for (int mt = 0; mt < 2; mt++) {
        int mrow = m0 + wm * 32 + mt * 16 + lq;
#pragma unroll
        for (int nt = 0; nt < 8; nt++) {
            int n = n0 + wn * 64 + nt * 8 + lr4 * 2;
            float s0 = gv[n]     * rsqrtf(vv[n]     + EPS);
            float s1 = gv[n + 1] * rsqrtf(vv[n + 1] + EPS);
            float m_0 = mv[n], m_1 = mv[n + 1];
            float o_0 = bv[n], o_1 = bv[n + 1];
            const float* cc = acc[mt][nt];
            float2 r0 = { (cc[0] - m_0) * s0 + o_0, (cc[1] - m_1) * s1 + o_1 };
            float2 r1 = { (cc[2] - m_0) * s0 + o_0, (cc[3] - m_1) * s1 + o_1 };
            *(float2*)(out + (size_t)mrow * Ncols + n)       = r0;
            *(float2*)(out + (size_t)(mrow + 8) * Ncols + n) = r1;
        }
    }
}

// ---------------------------------------------------------------------------
// Bias gather precompute: g_bias_buf[h][q][k] = biases[h, bias_idxs[q,k]]
// ---------------------------------------------------------------------------
__global__ void bias_gather(const float* __restrict__ biases,
                            const int* __restrict__ bidx)
{
    const int q = blockIdx.x;
    const int h = blockIdx.y;
    for (int k = threadIdx.x; k < NN; k += blockDim.x)
        g_bias_buf[(h * NQ + q) * NN + k] = biases[h * NN + bidx[q * NN + k]];
}

// ---------------------------------------------------------------------------
// Attention: one block per (batch, head). 256 threads = 8 warps.
// Bias pre-gathered (linear L2-resident loads). 4-way split AV accumulators.
// ---------------------------------------------------------------------------
__global__ __launch_bounds__(256)
void attn_kernel()
{
    __shared__ float ks[NN * 17];       // padded stride 17 -> conflict-free dot
    __shared__ float vs[NN * VD];
    __shared__ float qs[NQ * KD];
    __shared__ float ps[8 * NN];

    const int bh = blockIdx.x;
    const int b = bh >> 3, h = bh & 7;
    const int t = threadIdx.x;

    const float* kvbase = g_kv_buf + (size_t)b * NN * KV_DIM + h * (KD + VD);
    for (int idx = t; idx < NN * KD; idx += 256) {
        int n = idx >> 4, d = idx & 15;
        ks[n * 17 + d] = kvbase[n * KV_DIM + d];
    }
    for (int idx = t; idx < NN * VD; idx += 256) {
        int n = idx >> 5, d = idx & 31;
        vs[idx] = kvbase[n * KV_DIM + KD + d];
    }
    const float* qbase = g_q_buf + (size_t)b * NQ * Q_DIM + h * KD;
    for (int idx = t; idx < NQ * KD; idx += 256) {
        int n = idx >> 4, d = idx & 15;
        qs[idx] = qbase[n * Q_DIM + d];
    }
    __syncthreads();

    const int w = t >> 5, lane = t & 31;

    for (int q = w; q < NQ; q += 8) {
        const float* bsq = g_bias_buf + (h * NQ + q) * NN;
        float lg[7];
        float mx = -1e30f;
#pragma unroll
        for (int s = 0; s < 7; s++) {
            int k = lane + 32 * s;
            if (k < NN) {
                float d0 = 0.0f;
#pragma unroll
                for (int d = 0; d < KD; d++)
                    d0 += qs[q * KD + d] * ks[k * 17 + d];
                lg[s] = d0 * ATT_SCALE + __ldg(bsq + k);
                mx = fmaxf(mx, lg[s]);
            } else {
                lg[s] = -1e30f;
            }
        }
#pragma unroll
        for (int o = 16; o > 0; o >>= 1)
            mx = fmaxf(mx, __shfl_xor_sync(0xffffffffu, mx, o));
        float sum = 0.0f;
#pragma unroll
        for (int s = 0; s < 7; s++) {
            int k = lane + 32 * s;
            if (k < NN) { lg[s] = expf(lg[s] - mx); sum += lg[s]; }
        }
#pragma unroll
        for (int o = 16; o > 0; o >>= 1)
            sum += __shfl_xor_sync(0xffffffffu, sum, o);
        float inv = 1.0f / sum;
#pragma unroll
        for (int s = 0; s < 7; s++) {
            int k = lane + 32 * s;
            if (k < NN) ps[w * NN + k] = lg[s] * inv;
        }
        __syncwarp();
        // o[q, vd=lane] = sum_k p[k] * v[k, lane]; 4 independent chains (196=4*49)
        float ov0 = 0.0f, ov1 = 0.0f, ov2 = 0.0f, ov3 = 0.0f;
        const float* pw = ps + w * NN;
#pragma unroll 7
        for (int k = 0; k < 49; k++) {
            ov0 += pw[k      ] * vs[(k      ) * VD + lane];
            ov1 += pw[k +  49] * vs[(k +  49) * VD + lane];
            ov2 += pw[k +  98] * vs[(k +  98) * VD + lane];
            ov3 += pw[k + 147] * vs[(k + 147) * VD + lane];
        }
        g_o_buf[((size_t)(b * NQ + q)) * V_ATTN + h * VD + lane] =
            (ov0 + ov1) + (ov2 + ov3);
        __syncwarp();
    }
}

// ---------------------------------------------------------------------------
extern "C" void kernel_launch(void* const* d_in, const int* in_sizes, int n_in,
                              void* d_out, int out_size)
{
    const float* x      = (const float*)d_in[0];
    const float* W_kv   = (const float*)d_in[1];
    const float* gkv    = (const float*)d_in[2];
    const float* bkv    = (const float*)d_in[3];
    const float* mkv    = (const float*)d_in[4];
    const float* vkv    = (const float*)d_in[5];
    const float* W_q    = (const float*)d_in[6];
    const float* gq     = (const float*)d_in[7];
    const float* bq     = (const float*)d_in[8];
    const float* mq     = (const float*)d_in[9];
    const float* vq     = (const float*)d_in[10];
    const float* W_proj = (const float*)d_in[11];
    const float* gp     = (const float*)d_in[12];
    const float* bp     = (const float*)d_in[13];
    const float* mp     = (const float*)d_in[14];
    const float* vp     = (const float*)d_in[15];
    const float* biases = (const float*)d_in[16];
    const int*   bidx   = (const int*)  d_in[17];

    float *kvp, *qp, *op;
    cudaGetSymbolAddress((void**)&kvp, g_kv_buf);
    cudaGetSymbolAddress((void**)&qp,  g_q_buf);
    cudaGetSymbolAddress((void**)&op,  g_o_buf);

    // K0: bias gather table (tiny)
    bias_gather<<<dim3(NQ, HH), 196>>>(biases, bidx);

    // K1: kv = linear_norm(x, W_kv)  -- M=100352, N=384, K=256  (tf32 MMA)
    gemm_tf32<0><<<dim3(KV_DIM / 128, (BB * NN) / 128), 256>>>(
        x, W_kv, gkv, bkv, mkv, vkv, kvp, KV_DIM);

    // K2: q = linear_norm(subsample(x), W_q) -- M=25088, N=128 (tf32 MMA)
    gemm_tf32<1><<<dim3(Q_DIM / 128, (BB * NQ) / 128), 256>>>(
        x, W_q, gq, bq, mq, vq, qp, Q_DIM);

    // K3: attention per (b, h)
    attn_kernel<<<BB * HH, 256>>>();

    // K4: out = linear_norm(hardswish(o), W_proj) -- tf32 MMA
    gemm_tf32<2><<<dim3(OUT_DIM / 128, (BB * NQ) / 128), 256>>>(
        op, W_proj, gp, bp, mp, vp, (float*)d_out, OUT_DIM);
}